// round 1
// baseline (speedup 1.0000x reference)
#include <cuda_runtime.h>
#include <math.h>

// Problem constants (fixed by setup_inputs)
#define T_TOK 2048
#define DDIM  2048
#define NEXP  16
#define IDIM  1024
#define SIDIM 2048
#define KTOP  4

// GEMM tiling
#define BM 128
#define BN 64
#define BK 16

// ---------------- scratch (allocation-free: __device__ globals) ----------------
__device__ float g_h_shared[(size_t)T_TOK * SIDIM];          // 16.8 MB
__device__ float g_h_moe[(size_t)T_TOK * KTOP * IDIM];       // 33.5 MB
__device__ float g_y_moe[(size_t)T_TOK * KTOP * DDIM];       // 67 MB
__device__ int   g_counts[NEXP];
__device__ int   g_rows[NEXP * T_TOK];                       // per-expert slot lists
__device__ float g_slotw[T_TOK * KTOP];                      // normalized combine weights

// ---------------- init ----------------
__global__ void init_kernel() {
    if (threadIdx.x < NEXP) g_counts[threadIdx.x] = 0;
}

// ---------------- router: one warp per token ----------------
__global__ void router_kernel(const float* __restrict__ x,
                              const float* __restrict__ gw,
                              const float* __restrict__ gb) {
    int wid  = threadIdx.x >> 5;
    int lane = threadIdx.x & 31;
    int t = blockIdx.x * (blockDim.x >> 5) + wid;
    if (t >= T_TOK) return;

    float acc[NEXP];
#pragma unroll
    for (int e = 0; e < NEXP; e++) acc[e] = 0.f;

    const float* xr = x + (size_t)t * DDIM;
    for (int j = lane; j < DDIM; j += 32) {
        float xv = xr[j];
#pragma unroll
        for (int e = 0; e < NEXP; e++) acc[e] += xv * gw[e * DDIM + j];
    }
#pragma unroll
    for (int e = 0; e < NEXP; e++) {
#pragma unroll
        for (int off = 16; off > 0; off >>= 1)
            acc[e] += __shfl_xor_sync(0xffffffffu, acc[e], off);
    }

    // softmax over 16 logits (all lanes redundantly)
    float mx = acc[0];
#pragma unroll
    for (int e = 1; e < NEXP; e++) mx = fmaxf(mx, acc[e]);
    float p[NEXP];
    float sum = 0.f;
#pragma unroll
    for (int e = 0; e < NEXP; e++) { p[e] = expf(acc[e] - mx); sum += p[e]; }
    float inv = 1.f / sum;
#pragma unroll
    for (int e = 0; e < NEXP; e++) p[e] *= inv;

    // bias-corrected selection scores
    float bmin = gb[0];
#pragma unroll
    for (int e = 1; e < NEXP; e++) bmin = fminf(bmin, gb[e]);
    float sel[NEXP];
#pragma unroll
    for (int e = 0; e < NEXP; e++) sel[e] = p[e] + (gb[e] - bmin);

    // top-4 by biased score, weights from unbiased probs; first-index tie-break
    int   idx[KTOP];
    float w[KTOP];
    float wsum = 0.f;
#pragma unroll
    for (int s = 0; s < KTOP; s++) {
        int best = 0; float bv = sel[0];
#pragma unroll
        for (int e = 1; e < NEXP; e++) { if (sel[e] > bv) { bv = sel[e]; best = e; } }
        idx[s] = best; w[s] = p[best]; wsum += p[best];
        sel[best] = -1e30f;
    }
    float invw = 1.f / wsum;

    if (lane == 0) {
#pragma unroll
        for (int s = 0; s < KTOP; s++) {
            int slot = t * KTOP + s;
            g_slotw[slot] = w[s] * invw;
            int pos = atomicAdd(&g_counts[idx[s]], 1);
            g_rows[idx[s] * T_TOK + pos] = slot;
        }
    }
}

// ---------------- generic fp32 GEMM ----------------
// C[crow, :] = A[arow, :] @ B  (+ fused SwiGLU over paired g/u columns, optional
// row gather with per-expert weight lists, optional combine-weight scaling).
// GATHER: blockIdx.z = expert; rows list / counts / weights come from globals.
// SHIFT : arow = slot >> SHIFT (2: token from slot for gate_up; 0: slot itself).
template <bool GATHER, bool SWIGLU, bool SCALE, int SHIFT>
__launch_bounds__(256)
__global__ void gemm_kernel(const float* __restrict__ A,
                            const float* __restrict__ Bmat,
                            float* __restrict__ C,
                            int M, int K, int lda, int ldb, int ldc,
                            long long bstride, int uoff)
{
    const int* rows = nullptr;
    int n = M;
    const float* B = Bmat;
    if (GATHER) {
        int e = blockIdx.z;
        rows = g_rows + e * T_TOK;
        n = g_counts[e];
        B = Bmat + (long long)e * bstride;
        if ((int)(blockIdx.y * BM) >= n) return;   // uniform early exit
    }

    __shared__ float Ast[BK][BM];
    __shared__ float Bg[BK][BN];
    __shared__ float Bu[BK][BN];   // unused when !SWIGLU (4KB, harmless)

    const int tid = threadIdx.x;
    const int tx = tid & 15;        // N dim, 4 cols each
    const int ty = tid >> 4;        // M dim, 8 rows each
    const int row0 = blockIdx.y * BM;
    const int c0   = blockIdx.x * BN;

    // Precompute A-load descriptors: 2 float4 loads/thread
    long long aRowOff[2];
    int  aM[2], aK[2];
    bool aValid[2];
#pragma unroll
    for (int i = 0; i < 2; i++) {
        int f4 = tid + i * 256;
        int m  = f4 >> 2;
        aM[i] = m;
        aK[i] = (f4 & 3) * 4;
        int r = row0 + m;
        if (GATHER) {
            if (r < n) { int slot = rows[r]; aRowOff[i] = (long long)(slot >> SHIFT) * lda; aValid[i] = true; }
            else       { aRowOff[i] = 0; aValid[i] = false; }
        } else {
            aValid[i] = (r < M);
            aRowOff[i] = (long long)r * lda;
        }
    }
    const int kb = tid >> 4;          // B tile row 0..15
    const int bc = (tid & 15) * 4;    // B tile col

    float accg[8][4];
    float accu[8][4];
#pragma unroll
    for (int i = 0; i < 8; i++)
#pragma unroll
        for (int j = 0; j < 4; j++) { accg[i][j] = 0.f; accu[i][j] = 0.f; }

    for (int k0 = 0; k0 < K; k0 += BK) {
        // A -> smem (transposed to [BK][BM])
#pragma unroll
        for (int i = 0; i < 2; i++) {
            float4 v = make_float4(0.f, 0.f, 0.f, 0.f);
            if (aValid[i]) v = *(const float4*)(A + aRowOff[i] + k0 + aK[i]);
            Ast[aK[i] + 0][aM[i]] = v.x;
            Ast[aK[i] + 1][aM[i]] = v.y;
            Ast[aK[i] + 2][aM[i]] = v.z;
            Ast[aK[i] + 3][aM[i]] = v.w;
        }
        // B -> smem (gate cols, and up cols at +uoff when SWIGLU)
        {
            const float* bp = B + (long long)(k0 + kb) * ldb + c0 + bc;
            *(float4*)&Bg[kb][bc] = *(const float4*)bp;
            if (SWIGLU)
                *(float4*)&Bu[kb][bc] = *(const float4*)(bp + uoff);
        }
        __syncthreads();

#pragma unroll
        for (int kk = 0; kk < BK; kk++) {
            float a[8];
            *(float4*)&a[0] = *(const float4*)&Ast[kk][ty * 8];
            *(float4*)&a[4] = *(const float4*)&Ast[kk][ty * 8 + 4];
            float bg[4];
            *(float4*)&bg[0] = *(const float4*)&Bg[kk][tx * 4];
            float bu[4];
            if (SWIGLU) *(float4*)&bu[0] = *(const float4*)&Bu[kk][tx * 4];
#pragma unroll
            for (int i = 0; i < 8; i++) {
#pragma unroll
                for (int j = 0; j < 4; j++) {
                    accg[i][j] += a[i] * bg[j];
                    if (SWIGLU) accu[i][j] += a[i] * bu[j];
                }
            }
        }
        __syncthreads();
    }

    // epilogue
#pragma unroll
    for (int i = 0; i < 8; i++) {
        int r = row0 + ty * 8 + i;
        if (r >= n) continue;
        long long crow;
        float scale = 1.f;
        if (GATHER) {
            int slot = rows[r];
            crow = slot;
            if (SCALE) scale = g_slotw[slot];
        } else {
            crow = r;
        }
        float4 o;
        float v[4];
        if (SWIGLU) {
#pragma unroll
            for (int j = 0; j < 4; j++) {
                float g = accg[i][j];
                float s = 1.f / (1.f + expf(-g));
                v[j] = g * s * accu[i][j];
            }
        } else {
#pragma unroll
            for (int j = 0; j < 4; j++) v[j] = accg[i][j] * scale;
        }
        o.x = v[0]; o.y = v[1]; o.z = v[2]; o.w = v[3];
        *(float4*)(C + crow * (long long)ldc + c0 + tx * 4) = o;
    }
}

// ---------------- combine: out[t] += sum_s y_moe[4t+s] (pre-scaled) ----------------
__global__ void combine_kernel(float* __restrict__ out) {
    long long i = (long long)blockIdx.x * blockDim.x + threadIdx.x; // float4 index
    const long long nf4 = (long long)T_TOK * DDIM / 4;
    if (i >= nf4) return;
    long long t = i / (DDIM / 4);
    int c = (int)(i % (DDIM / 4)) * 4;
    float4 o = *(float4*)(out + t * DDIM + c);
#pragma unroll
    for (int s = 0; s < KTOP; s++) {
        const float4 y = *(const float4*)(g_y_moe + ((t * KTOP + s) * (long long)DDIM) + c);
        o.x += y.x; o.y += y.y; o.z += y.z; o.w += y.w;
    }
    *(float4*)(out + t * DDIM + c) = o;
}

// ---------------- host ----------------
static float* sym_f(const void* symbol) {
    void* p = nullptr;
    cudaGetSymbolAddress(&p, symbol);
    return (float*)p;
}

extern "C" void kernel_launch(void* const* d_in, const int* in_sizes, int n_in,
                              void* d_out, int out_size) {
    (void)in_sizes; (void)n_in; (void)out_size;
    const float* x    = (const float*)d_in[0];
    const float* gw   = (const float*)d_in[1];
    const float* gb   = (const float*)d_in[2];
    const float* wgu  = (const float*)d_in[3];
    const float* wd   = (const float*)d_in[4];
    const float* wsgu = (const float*)d_in[5];
    const float* wsd  = (const float*)d_in[6];
    float* out = (float*)d_out;

    float* h_shared = sym_f(g_h_shared);
    float* h_moe    = sym_f(g_h_moe);
    float* y_moe    = sym_f(g_y_moe);

    init_kernel<<<1, 32>>>();
    router_kernel<<<T_TOK / 8, 256>>>(x, gw, gb);

    // shared expert gate_up + SwiGLU: [T,D]@[D,2SI] -> h_shared [T,SI]
    gemm_kernel<false, true, false, 0>
        <<<dim3(SIDIM / BN, T_TOK / BM, 1), 256>>>(
            x, wsgu, h_shared,
            T_TOK, DDIM, DDIM, 2 * SIDIM, SIDIM, 0, SIDIM);

    // shared expert down: [T,SI]@[SI,D] -> out (dense write covers poison)
    gemm_kernel<false, false, false, 0>
        <<<dim3(DDIM / BN, T_TOK / BM, 1), 256>>>(
            h_shared, wsd, out,
            T_TOK, SIDIM, SIDIM, DDIM, DDIM, 0, 0);

    // routed gate_up + SwiGLU (gathered): x[token]@Wgu_e -> h_moe[slot, I]
    gemm_kernel<true, true, false, 2>
        <<<dim3(IDIM / BN, T_TOK / BM, NEXP), 256>>>(
            x, wgu, h_moe,
            0, DDIM, DDIM, 2 * IDIM, IDIM,
            (long long)DDIM * 2 * IDIM, IDIM);

    // routed down (gathered, combine-weight scaled): h_moe[slot]@Wd_e -> y_moe[slot, D]
    gemm_kernel<true, false, true, 0>
        <<<dim3(DDIM / BN, T_TOK / BM, NEXP), 256>>>(
            h_moe, wd, y_moe,
            0, IDIM, IDIM, DDIM, DDIM,
            (long long)IDIM * DDIM, 0);

    // out += sum over 4 slots
    combine_kernel<<<(T_TOK * DDIM / 4 + 255) / 256, 256>>>(out);
}

// round 3
// speedup vs baseline: 2.3505x; 2.3505x over previous
#include <cuda_runtime.h>
#include <math.h>
#include <stdint.h>

// Problem constants
#define T_TOK 2048
#define DDIM  2048
#define NEXP  16
#define IDIM  1024
#define SIDIM 2048
#define KTOP  4

// ---------------- scratch (__device__ globals, allocation-free) ----------------
__device__ float g_h_shared[(size_t)T_TOK * SIDIM];
__device__ float g_h_moe[(size_t)T_TOK * KTOP * IDIM];
__device__ float g_y_moe[(size_t)T_TOK * KTOP * DDIM];
__device__ int   g_counts[NEXP];
__device__ int   g_rows[NEXP * T_TOK];
__device__ float g_slotw[T_TOK * KTOP];

// ---------------- helpers ----------------
__device__ __forceinline__ uint32_t f2tf(float f) {
    uint32_t r;
    asm("cvt.rna.tf32.f32 %0, %1;" : "=r"(r) : "f"(f));
    return r;
}
__device__ __forceinline__ uint4 cvt4(float4 v) {
    uint4 t;
    t.x = f2tf(v.x); t.y = f2tf(v.y); t.z = f2tf(v.z); t.w = f2tf(v.w);
    return t;
}
__device__ __forceinline__ void mma8(float c[4], const uint32_t a[4], const uint32_t b[2]) {
    asm volatile(
        "mma.sync.aligned.m16n8k8.row.col.f32.tf32.tf32.f32 "
        "{%0,%1,%2,%3}, {%4,%5,%6,%7}, {%8,%9}, {%0,%1,%2,%3};"
        : "+f"(c[0]), "+f"(c[1]), "+f"(c[2]), "+f"(c[3])
        : "r"(a[0]), "r"(a[1]), "r"(a[2]), "r"(a[3]), "r"(b[0]), "r"(b[1]));
}

// smem layout (uint32 words): per buffer: A 4096 words (128 rows x 32, swizzled)
// + B 4352 words (32 rows x 136 incl. 8-word pad)  => 8448 words; x2 buffers.
#define BUF_WORDS 8448
#define SM_BYTES  (2 * BUF_WORDS * 4)   // 67584

// ---------------- init + router ----------------
__global__ void init_kernel() {
    if (threadIdx.x < NEXP) g_counts[threadIdx.x] = 0;
}

__global__ void router_kernel(const float* __restrict__ x,
                              const float* __restrict__ gw,
                              const float* __restrict__ gb) {
    int wid  = threadIdx.x >> 5;
    int lane = threadIdx.x & 31;
    int t = blockIdx.x * (blockDim.x >> 5) + wid;
    if (t >= T_TOK) return;

    float acc[NEXP];
#pragma unroll
    for (int e = 0; e < NEXP; e++) acc[e] = 0.f;
    const float* xr = x + (size_t)t * DDIM;
    for (int j = lane; j < DDIM; j += 32) {
        float xv = xr[j];
#pragma unroll
        for (int e = 0; e < NEXP; e++) acc[e] += xv * gw[e * DDIM + j];
    }
#pragma unroll
    for (int e = 0; e < NEXP; e++) {
#pragma unroll
        for (int off = 16; off > 0; off >>= 1)
            acc[e] += __shfl_xor_sync(0xffffffffu, acc[e], off);
    }
    float mx = acc[0];
#pragma unroll
    for (int e = 1; e < NEXP; e++) mx = fmaxf(mx, acc[e]);
    float p[NEXP]; float sum = 0.f;
#pragma unroll
    for (int e = 0; e < NEXP; e++) { p[e] = expf(acc[e] - mx); sum += p[e]; }
    float inv = 1.f / sum;
#pragma unroll
    for (int e = 0; e < NEXP; e++) p[e] *= inv;
    float bmin = gb[0];
#pragma unroll
    for (int e = 1; e < NEXP; e++) bmin = fminf(bmin, gb[e]);
    float sel[NEXP];
#pragma unroll
    for (int e = 0; e < NEXP; e++) sel[e] = p[e] + (gb[e] - bmin);
    int idx[KTOP]; float w[KTOP]; float wsum = 0.f;
#pragma unroll
    for (int s = 0; s < KTOP; s++) {
        int best = 0; float bv = sel[0];
#pragma unroll
        for (int e = 1; e < NEXP; e++) { if (sel[e] > bv) { bv = sel[e]; best = e; } }
        idx[s] = best; w[s] = p[best]; wsum += p[best];
        sel[best] = -1e30f;
    }
    float invw = 1.f / wsum;
    if (lane == 0) {
#pragma unroll
        for (int s = 0; s < KTOP; s++) {
            int slot = t * KTOP + s;
            g_slotw[slot] = w[s] * invw;
            int pos = atomicAdd(&g_counts[idx[s]], 1);
            g_rows[idx[s] * T_TOK + pos] = slot;
        }
    }
}

// ---------------- tf32 mma.sync GEMM ----------------
// C[row,:] = A[row,:] @ B with B in gmem as [K,N] row-major.
// Block tile 128 x (SWIGLU?64:128) out cols x K, BK=32. 8 warps: 4(M) x 2(N).
// SWIGLU: B smem 128 cols interleave gate/up at 8-col tile granularity so each
// warp owns matching g/u accumulators; epilogue writes silu(g)*u.
// GATHER: blockIdx.z = expert; rows from g_rows; SHIFT maps slot->A row.
// SCALE : epilogue multiplies by g_slotw[slot].
template <bool GATHER, bool SWIGLU, bool SCALE, int SHIFT>
__global__ void __launch_bounds__(256)
tgemm(const float* __restrict__ A, const float* __restrict__ Bmat,
      float* __restrict__ C, int K, int lda, int ldb, int ldc,
      long long bstride, int uoff)
{
    int n = 0x7fffffff;
    const int* rowlist = nullptr;
    const float* B = Bmat;
    if (GATHER) {
        int e = blockIdx.z;
        n = g_counts[e];
        if ((int)(blockIdx.y * 128) >= n) return;
        rowlist = g_rows + e * T_TOK;
        B = Bmat + (long long)e * bstride;
    }

    extern __shared__ uint32_t smem[];
    const int tid = threadIdx.x;
    const int wid = tid >> 5, lane = tid & 31;
    const int gid = lane >> 2, tig = lane & 3;
    const int wm = wid & 3, wn = wid >> 2;
    const int row0 = blockIdx.y * 128;
    const int BNout = SWIGLU ? 64 : 128;
    const int c0 = blockIdx.x * BNout;

    // ---- staging descriptors (element offsets fit in int) ----
    int aoff[4]; bool aval[4]; int asw[4];
#pragma unroll
    for (int i = 0; i < 4; i++) {
        int f4 = tid + i * 256;
        int m = f4 >> 3, k4 = f4 & 7;
        asw[i] = m * 32 + ((k4 ^ (m & 7)) << 2);
        int r = row0 + m;
        if (GATHER) {
            if (r < n) { aoff[i] = (rowlist[r] >> SHIFT) * lda + k4 * 4; aval[i] = true; }
            else       { aoff[i] = 0; aval[i] = false; }
        } else { aoff[i] = r * lda + k4 * 4; aval[i] = true; }
    }
    int boff[4]; int bsw[4];
#pragma unroll
    for (int i = 0; i < 4; i++) {
        int f4 = tid + i * 256;
        int k = f4 >> 5, n4 = f4 & 31;
        int gcol;
        if (SWIGLU) {
            int t  = n4 >> 2;
            int up = (n4 >> 1) & 1;
            int ci = (n4 & 1) * 4;
            gcol = (up ? uoff : 0) + c0 + t * 8 + ci;
        } else {
            gcol = c0 + n4 * 4;
        }
        boff[i] = k * ldb + gcol;
        bsw[i] = 4096 + k * 136 + n4 * 4;
    }

    float acc[2][8][4];
#pragma unroll
    for (int mt = 0; mt < 2; mt++)
#pragma unroll
        for (int j = 0; j < 8; j++)
#pragma unroll
            for (int q = 0; q < 4; q++) acc[mt][j][q] = 0.f;

    const int NC = K / 32;

    // stage chunk 0
    {
        const float4 z4 = make_float4(0.f, 0.f, 0.f, 0.f);
#pragma unroll
        for (int i = 0; i < 4; i++) {
            float4 v = aval[i] ? *(const float4*)(A + aoff[i]) : z4;
            *(uint4*)(smem + asw[i]) = cvt4(v);
        }
#pragma unroll
        for (int i = 0; i < 4; i++) {
            float4 v = *(const float4*)(B + boff[i]);
            *(uint4*)(smem + bsw[i]) = cvt4(v);
        }
    }
    __syncthreads();

    for (int ch = 0; ch < NC; ch++) {
        float4 pa[4], pb[4];
        const int nxt = ch + 1;
        if (nxt < NC) {
            const float4 z4 = make_float4(0.f, 0.f, 0.f, 0.f);
            const int ka = nxt * 32;
            const int kb = nxt * 32 * ldb;
#pragma unroll
            for (int i = 0; i < 4; i++)
                pa[i] = aval[i] ? *(const float4*)(A + aoff[i] + ka) : z4;
#pragma unroll
            for (int i = 0; i < 4; i++)
                pb[i] = *(const float4*)(B + boff[i] + kb);
        }

        const uint32_t* As = smem + (ch & 1) * BUF_WORDS;
        const uint32_t* Bs = As + 4096;
        const int msw = gid & 7;
#pragma unroll
        for (int ks = 0; ks < 4; ks++) {
            uint32_t a[2][4];
            const int c0w = ((ks * 2) ^ msw) << 2;
            const int c1w = ((ks * 2 + 1) ^ msw) << 2;
#pragma unroll
            for (int mt = 0; mt < 2; mt++) {
                const uint32_t* ap = As + (wm * 32 + mt * 16 + gid) * 32;
                a[mt][0] = ap[c0w + tig];
                a[mt][1] = ap[256 + c0w + tig];
                a[mt][2] = ap[c1w + tig];
                a[mt][3] = ap[256 + c1w + tig];
            }
            uint32_t b[8][2];
            const uint32_t* bp = Bs + (ks * 8 + tig) * 136 + wn * 64 + gid;
#pragma unroll
            for (int j = 0; j < 8; j++) {
                b[j][0] = bp[j * 8];
                b[j][1] = bp[544 + j * 8];   // +4 k-rows = +4*136 words
            }
#pragma unroll
            for (int mt = 0; mt < 2; mt++)
#pragma unroll
                for (int j = 0; j < 8; j++)
                    mma8(acc[mt][j], a[mt], b[j]);
        }

        if (nxt < NC) {
            uint32_t* db = smem + (nxt & 1) * BUF_WORDS;
#pragma unroll
            for (int i = 0; i < 4; i++) *(uint4*)(db + asw[i]) = cvt4(pa[i]);
#pragma unroll
            for (int i = 0; i < 4; i++) *(uint4*)(db + bsw[i]) = cvt4(pb[i]);
        }
        __syncthreads();
    }

    // ---- epilogue ----
#pragma unroll
    for (int mt = 0; mt < 2; mt++) {
#pragma unroll
        for (int h = 0; h < 2; h++) {
            int r = row0 + wm * 32 + mt * 16 + gid + h * 8;
            bool valid = GATHER ? (r < n) : true;
            if (!valid) continue;
            int crow; float scale = 1.f;
            if (GATHER) {
                int slot = rowlist[r];
                crow = slot;
                if (SCALE) scale = g_slotw[slot];
            } else crow = r;
            float* cp = C + (long long)crow * ldc;
            if (SWIGLU) {
#pragma unroll
                for (int t2 = 0; t2 < 4; t2++) {
                    float g0 = acc[mt][t2 * 2][h * 2 + 0];
                    float g1 = acc[mt][t2 * 2][h * 2 + 1];
                    float u0 = acc[mt][t2 * 2 + 1][h * 2 + 0];
                    float u1 = acc[mt][t2 * 2 + 1][h * 2 + 1];
                    float2 o;
                    o.x = g0 / (1.f + expf(-g0)) * u0;
                    o.y = g1 / (1.f + expf(-g1)) * u1;
                    *(float2*)(cp + c0 + (wn * 4 + t2) * 8 + tig * 2) = o;
                }
            } else {
#pragma unroll
                for (int j = 0; j < 8; j++) {
                    float2 o;
                    o.x = acc[mt][j][h * 2 + 0] * scale;
                    o.y = acc[mt][j][h * 2 + 1] * scale;
                    *(float2*)(cp + c0 + (wn * 8 + j) * 8 + tig * 2) = o;
                }
            }
        }
    }
}

// ---------------- combine: out[t] += sum_s y_moe[4t+s] ----------------
__global__ void combine_kernel(float* __restrict__ out) {
    long long i = (long long)blockIdx.x * blockDim.x + threadIdx.x;
    const long long nf4 = (long long)T_TOK * DDIM / 4;
    if (i >= nf4) return;
    long long t = i / (DDIM / 4);
    int c = (int)(i % (DDIM / 4)) * 4;
    float4 o = *(float4*)(out + t * DDIM + c);
#pragma unroll
    for (int s = 0; s < KTOP; s++) {
        const float4 y = *(const float4*)(g_y_moe + ((t * KTOP + s) * (long long)DDIM) + c);
        o.x += y.x; o.y += y.y; o.z += y.z; o.w += y.w;
    }
    *(float4*)(out + t * DDIM + c) = o;
}

// ---------------- host ----------------
static float* sym_f(const void* symbol) {
    void* p = nullptr;
    cudaGetSymbolAddress(&p, symbol);
    return (float*)p;
}

extern "C" void kernel_launch(void* const* d_in, const int* in_sizes, int n_in,
                              void* d_out, int out_size) {
    (void)in_sizes; (void)n_in; (void)out_size;
    const float* x    = (const float*)d_in[0];
    const float* gw   = (const float*)d_in[1];
    const float* gb   = (const float*)d_in[2];
    const float* wgu  = (const float*)d_in[3];
    const float* wd   = (const float*)d_in[4];
    const float* wsgu = (const float*)d_in[5];
    const float* wsd  = (const float*)d_in[6];
    float* out = (float*)d_out;

    float* h_shared = sym_f(g_h_shared);
    float* h_moe    = sym_f(g_h_moe);
    float* y_moe    = sym_f(g_y_moe);

    cudaFuncSetAttribute(tgemm<false, true,  false, 0>, cudaFuncAttributeMaxDynamicSharedMemorySize, SM_BYTES);
    cudaFuncSetAttribute(tgemm<false, false, false, 0>, cudaFuncAttributeMaxDynamicSharedMemorySize, SM_BYTES);
    cudaFuncSetAttribute(tgemm<true,  true,  false, 2>, cudaFuncAttributeMaxDynamicSharedMemorySize, SM_BYTES);
    cudaFuncSetAttribute(tgemm<true,  false, true,  0>, cudaFuncAttributeMaxDynamicSharedMemorySize, SM_BYTES);

    init_kernel<<<1, 32>>>();
    router_kernel<<<T_TOK / 8, 256>>>(x, gw, gb);

    // shared gate_up + SwiGLU: x[T,D] @ wsgu[D,2SI] -> h_shared[T,SI]
    tgemm<false, true, false, 0>
        <<<dim3(SIDIM / 64, T_TOK / 128, 1), 256, SM_BYTES>>>(
            x, wsgu, h_shared, DDIM, DDIM, 2 * SIDIM, SIDIM, 0, SIDIM);

    // shared down: h_shared[T,SI] @ wsd[SI,D] -> out (dense write covers poison)
    tgemm<false, false, false, 0>
        <<<dim3(DDIM / 128, T_TOK / 128, 1), 256, SM_BYTES>>>(
            h_shared, wsd, out, SIDIM, SIDIM, DDIM, DDIM, 0, 0);

    // routed gate_up + SwiGLU (gather tokens): x @ wgu[e] -> h_moe[slot, I]
    tgemm<true, true, false, 2>
        <<<dim3(IDIM / 64, T_TOK / 128, NEXP), 256, SM_BYTES>>>(
            x, wgu, h_moe, DDIM, DDIM, 2 * IDIM, IDIM,
            (long long)DDIM * 2 * IDIM, IDIM);

    // routed down (gather slots, scale): h_moe @ wd[e] -> y_moe[slot, D]
    tgemm<true, false, true, 0>
        <<<dim3(DDIM / 128, T_TOK / 128, NEXP), 256, SM_BYTES>>>(
            h_moe, wd, y_moe, IDIM, IDIM, DDIM, DDIM,
            (long long)IDIM * DDIM, 0);

    combine_kernel<<<(T_TOK * DDIM / 4 + 255) / 256, 256>>>(out);
}

// round 4
// speedup vs baseline: 2.9206x; 1.2425x over previous
#include <cuda_runtime.h>
#include <math.h>
#include <stdint.h>

// Problem constants
#define T_TOK 2048
#define DDIM  2048
#define NEXP  16
#define IDIM  1024
#define SIDIM 2048
#define KTOP  4

// ---------------- scratch (__device__ globals, allocation-free) ----------------
__device__ float g_h_shared[(size_t)T_TOK * SIDIM];
__device__ float g_h_moe[(size_t)T_TOK * KTOP * IDIM];
__device__ float g_y_moe[(size_t)T_TOK * KTOP * DDIM];
__device__ int   g_counts[NEXP];
__device__ int   g_rows[NEXP * T_TOK];
__device__ float g_slotw[T_TOK * KTOP];
// tf32-preconverted operands
__device__ float g_x_t[(size_t)T_TOK * DDIM];                     // 16.8 MB
__device__ float g_wgu_t[(size_t)NEXP * DDIM * 2 * IDIM];         // 268 MB
__device__ float g_wd_t[(size_t)NEXP * IDIM * DDIM];              // 134 MB
__device__ float g_wsgu_t[(size_t)DDIM * 2 * SIDIM];              // 33.5 MB
__device__ float g_wsd_t[(size_t)SIDIM * DDIM];                   // 16.8 MB

// ---------------- helpers ----------------
__device__ __forceinline__ uint32_t f2tf(float f) {
    uint32_t r;
    asm("cvt.rna.tf32.f32 %0, %1;" : "=r"(r) : "f"(f));
    return r;
}
__device__ __forceinline__ uint4 cvt4(float4 v) {
    uint4 t;
    t.x = f2tf(v.x); t.y = f2tf(v.y); t.z = f2tf(v.z); t.w = f2tf(v.w);
    return t;
}
__device__ __forceinline__ void mma8(float c[4], const uint32_t a[4], const uint32_t b[2]) {
    asm volatile(
        "mma.sync.aligned.m16n8k8.row.col.f32.tf32.tf32.f32 "
        "{%0,%1,%2,%3}, {%4,%5,%6,%7}, {%8,%9}, {%0,%1,%2,%3};"
        : "+f"(c[0]), "+f"(c[1]), "+f"(c[2]), "+f"(c[3])
        : "r"(a[0]), "r"(a[1]), "r"(a[2]), "r"(a[3]), "r"(b[0]), "r"(b[1]));
}
__device__ __forceinline__ uint32_t smem_u32(const void* p) {
    uint32_t a;
    asm("{ .reg .u64 t; cvta.to.shared.u64 t, %1; cvt.u32.u64 %0, t; }" : "=r"(a) : "l"(p));
    return a;
}
__device__ __forceinline__ void cp16(uint32_t saddr, const void* gptr, uint32_t sz) {
    asm volatile("cp.async.cg.shared.global [%0], [%1], 16, %2;"
                 :: "r"(saddr), "l"(gptr), "r"(sz) : "memory");
}
#define CP_COMMIT() asm volatile("cp.async.commit_group;" ::: "memory")
#define CP_WAIT2()  asm volatile("cp.async.wait_group 2;" ::: "memory")

// smem stage: A 4096 words + B 4352 words (32 rows x 136 incl pad) = 8448 words
#define STG_WORDS 8448
#define STG_BYTES (STG_WORDS * 4)          // 33792
#define SM_BYTES  (3 * STG_BYTES)          // 101376

// ---------------- conversion kernel: dst = tf32_rna(src) ----------------
__global__ void cvt_kernel(const float4* __restrict__ src, float4* __restrict__ dst, int n4) {
    int stride = gridDim.x * blockDim.x;
    for (int i = blockIdx.x * blockDim.x + threadIdx.x; i < n4; i += stride) {
        uint4 t = cvt4(src[i]);
        dst[i] = *(float4*)&t;
    }
}

// ---------------- init + router ----------------
__global__ void init_kernel() {
    if (threadIdx.x < NEXP) g_counts[threadIdx.x] = 0;
}

__global__ void router_kernel(const float* __restrict__ x,
                              const float* __restrict__ gw,
                              const float* __restrict__ gb) {
    int wid  = threadIdx.x >> 5;
    int lane = threadIdx.x & 31;
    int t = blockIdx.x * (blockDim.x >> 5) + wid;
    if (t >= T_TOK) return;

    float acc[NEXP];
#pragma unroll
    for (int e = 0; e < NEXP; e++) acc[e] = 0.f;
    const float* xr = x + (size_t)t * DDIM;
    for (int j = lane; j < DDIM; j += 32) {
        float xv = xr[j];
#pragma unroll
        for (int e = 0; e < NEXP; e++) acc[e] += xv * gw[e * DDIM + j];
    }
#pragma unroll
    for (int e = 0; e < NEXP; e++) {
#pragma unroll
        for (int off = 16; off > 0; off >>= 1)
            acc[e] += __shfl_xor_sync(0xffffffffu, acc[e], off);
    }
    float mx = acc[0];
#pragma unroll
    for (int e = 1; e < NEXP; e++) mx = fmaxf(mx, acc[e]);
    float p[NEXP]; float sum = 0.f;
#pragma unroll
    for (int e = 0; e < NEXP; e++) { p[e] = expf(acc[e] - mx); sum += p[e]; }
    float inv = 1.f / sum;
#pragma unroll
    for (int e = 0; e < NEXP; e++) p[e] *= inv;
    float bmin = gb[0];
#pragma unroll
    for (int e = 1; e < NEXP; e++) bmin = fminf(bmin, gb[e]);
    float sel[NEXP];
#pragma unroll
    for (int e = 0; e < NEXP; e++) sel[e] = p[e] + (gb[e] - bmin);
    int idx[KTOP]; float w[KTOP]; float wsum = 0.f;
#pragma unroll
    for (int s = 0; s < KTOP; s++) {
        int best = 0; float bv = sel[0];
#pragma unroll
        for (int e = 1; e < NEXP; e++) { if (sel[e] > bv) { bv = sel[e]; best = e; } }
        idx[s] = best; w[s] = p[best]; wsum += p[best];
        sel[best] = -1e30f;
    }
    float invw = 1.f / wsum;
    if (lane == 0) {
#pragma unroll
        for (int s = 0; s < KTOP; s++) {
            int slot = t * KTOP + s;
            g_slotw[slot] = w[s] * invw;
            int pos = atomicAdd(&g_counts[idx[s]], 1);
            g_rows[idx[s] * T_TOK + pos] = slot;
        }
    }
}

// ---------------- tf32 mma.sync GEMM (cp.async 3-stage, 2 CTA/SM) ----------------
// Operands are PRE-CONVERTED tf32-in-fp32. Block tile 128 x (SWIGLU?64:128) x K,
// BK=32, 8 warps (4M x 2N), warp tile 32x64.
// SWIGLU: B smem interleaves gate/up at 8-col granularity; epilogue silu(g)*u.
// GATHER: blockIdx.z = expert; SHIFT maps slot->A row.  SCALE: *g_slotw[slot].
// CVTOUT: round epilogue output to tf32 (for h_shared / h_moe feeding next GEMM).
template <bool GATHER, bool SWIGLU, bool SCALE, int SHIFT, bool CVTOUT>
__global__ void __launch_bounds__(256, 2)
tgemm(const float* __restrict__ A, const float* __restrict__ Bmat,
      float* __restrict__ C, int K, int lda, int ldb, int ldc,
      long long bstride, int uoff)
{
    int n = 0x7fffffff;
    const int* rowlist = nullptr;
    const float* B = Bmat;
    if (GATHER) {
        int e = blockIdx.z;
        n = g_counts[e];
        if ((int)(blockIdx.y * 128) >= n) return;
        rowlist = g_rows + e * T_TOK;
        B = Bmat + (long long)e * bstride;
    }

    extern __shared__ uint32_t smem[];
    const uint32_t sbase = smem_u32(smem);
    const int tid = threadIdx.x;
    const int wid = tid >> 5, lane = tid & 31;
    const int gid = lane >> 2, tig = lane & 3;
    const int wm = wid & 3, wn = wid >> 2;
    const int row0 = blockIdx.y * 128;
    const int BNout = SWIGLU ? 64 : 128;
    const int c0 = blockIdx.x * BNout;

    // staging descriptors: 4 A-chunks + 4 B-chunks of 16B per thread per stage
    int aoff[4]; uint32_t asz[4]; uint32_t asw[4];
#pragma unroll
    for (int i = 0; i < 4; i++) {
        int f4 = tid + i * 256;
        int m = f4 >> 3, k4 = f4 & 7;
        asw[i] = (uint32_t)(m * 32 + ((k4 ^ (m & 7)) << 2)) * 4;
        int r = row0 + m;
        if (GATHER) {
            if (r < n) { aoff[i] = (rowlist[r] >> SHIFT) * lda + k4 * 4; asz[i] = 16; }
            else       { aoff[i] = 0; asz[i] = 0; }
        } else { aoff[i] = r * lda + k4 * 4; asz[i] = 16; }
    }
    int boff[4]; uint32_t bsw[4];
#pragma unroll
    for (int i = 0; i < 4; i++) {
        int f4 = tid + i * 256;
        int k = f4 >> 5, n4 = f4 & 31;
        int gcol;
        if (SWIGLU) {
            int t  = n4 >> 2;
            int up = (n4 >> 1) & 1;
            int ci = (n4 & 1) * 4;
            gcol = (up ? uoff : 0) + c0 + t * 8 + ci;
        } else {
            gcol = c0 + n4 * 4;
        }
        boff[i] = k * ldb + gcol;
        bsw[i] = (uint32_t)(4096 + k * 136 + n4 * 4) * 4;
    }

    float acc[2][8][4];
#pragma unroll
    for (int mt = 0; mt < 2; mt++)
#pragma unroll
        for (int j = 0; j < 8; j++)
#pragma unroll
            for (int q = 0; q < 4; q++) acc[mt][j][q] = 0.f;

    const int NC = K / 32;

    // ---- issue helper (macro to keep regs low) ----
#define ISSUE(ch)                                                            \
    {                                                                        \
        const uint32_t sb_ = sbase + (uint32_t)((ch) % 3) * STG_BYTES;       \
        const int ka_ = (ch) * 32;                                           \
        const int kb_ = (ch) * 32 * ldb;                                     \
        _Pragma("unroll")                                                    \
        for (int i = 0; i < 4; i++) cp16(sb_ + asw[i], A + aoff[i] + ka_, asz[i]); \
        _Pragma("unroll")                                                    \
        for (int i = 0; i < 4; i++) cp16(sb_ + bsw[i], B + boff[i] + kb_, 16u); \
    }

    ISSUE(0); CP_COMMIT();
    ISSUE(1); CP_COMMIT();

    for (int ch = 0; ch < NC; ch++) {
        if (ch + 2 < NC) { ISSUE(ch + 2); }
        CP_COMMIT();
        CP_WAIT2();
        __syncthreads();

        const uint32_t* As = smem + (ch % 3) * STG_WORDS;
        const uint32_t* Bs = As + 4096;
        const int msw = gid & 7;
#pragma unroll
        for (int ks = 0; ks < 4; ks++) {
            uint32_t a[2][4];
            const int c0w = ((ks * 2) ^ msw) << 2;
            const int c1w = ((ks * 2 + 1) ^ msw) << 2;
#pragma unroll
            for (int mt = 0; mt < 2; mt++) {
                const uint32_t* ap = As + (wm * 32 + mt * 16 + gid) * 32;
                a[mt][0] = ap[c0w + tig];
                a[mt][1] = ap[256 + c0w + tig];
                a[mt][2] = ap[c1w + tig];
                a[mt][3] = ap[256 + c1w + tig];
            }
            uint32_t b[8][2];
            const uint32_t* bp = Bs + (ks * 8 + tig) * 136 + wn * 64 + gid;
#pragma unroll
            for (int j = 0; j < 8; j++) {
                b[j][0] = bp[j * 8];
                b[j][1] = bp[544 + j * 8];
            }
#pragma unroll
            for (int mt = 0; mt < 2; mt++)
#pragma unroll
                for (int j = 0; j < 8; j++)
                    mma8(acc[mt][j], a[mt], b[j]);
        }
        __syncthreads();
    }
#undef ISSUE

    // ---- epilogue ----
#pragma unroll
    for (int mt = 0; mt < 2; mt++) {
#pragma unroll
        for (int h = 0; h < 2; h++) {
            int r = row0 + wm * 32 + mt * 16 + gid + h * 8;
            bool valid = GATHER ? (r < n) : true;
            if (!valid) continue;
            int crow; float scale = 1.f;
            if (GATHER) {
                int slot = rowlist[r];
                crow = slot;
                if (SCALE) scale = g_slotw[slot];
            } else crow = r;
            float* cp = C + (long long)crow * ldc;
            if (SWIGLU) {
#pragma unroll
                for (int t2 = 0; t2 < 4; t2++) {
                    float g0 = acc[mt][t2 * 2][h * 2 + 0];
                    float g1 = acc[mt][t2 * 2][h * 2 + 1];
                    float u0 = acc[mt][t2 * 2 + 1][h * 2 + 0];
                    float u1 = acc[mt][t2 * 2 + 1][h * 2 + 1];
                    float2 o;
                    o.x = g0 / (1.f + expf(-g0)) * u0;
                    o.y = g1 / (1.f + expf(-g1)) * u1;
                    if (CVTOUT) {
                        o.x = __uint_as_float(f2tf(o.x));
                        o.y = __uint_as_float(f2tf(o.y));
                    }
                    *(float2*)(cp + c0 + (wn * 4 + t2) * 8 + tig * 2) = o;
                }
            } else {
#pragma unroll
                for (int j = 0; j < 8; j++) {
                    float2 o;
                    o.x = acc[mt][j][h * 2 + 0] * scale;
                    o.y = acc[mt][j][h * 2 + 1] * scale;
                    if (CVTOUT) {
                        o.x = __uint_as_float(f2tf(o.x));
                        o.y = __uint_as_float(f2tf(o.y));
                    }
                    *(float2*)(cp + c0 + (wn * 8 + j) * 8 + tig * 2) = o;
                }
            }
        }
    }
}

// ---------------- combine ----------------
__global__ void combine_kernel(float* __restrict__ out) {
    long long i = (long long)blockIdx.x * blockDim.x + threadIdx.x;
    const long long nf4 = (long long)T_TOK * DDIM / 4;
    if (i >= nf4) return;
    long long t = i / (DDIM / 4);
    int c = (int)(i % (DDIM / 4)) * 4;
    float4 o = *(float4*)(out + t * DDIM + c);
#pragma unroll
    for (int s = 0; s < KTOP; s++) {
        const float4 y = *(const float4*)(g_y_moe + ((t * KTOP + s) * (long long)DDIM) + c);
        o.x += y.x; o.y += y.y; o.z += y.z; o.w += y.w;
    }
    *(float4*)(out + t * DDIM + c) = o;
}

// ---------------- host ----------------
static float* sym_f(const void* symbol) {
    void* p = nullptr;
    cudaGetSymbolAddress(&p, symbol);
    return (float*)p;
}

extern "C" void kernel_launch(void* const* d_in, const int* in_sizes, int n_in,
                              void* d_out, int out_size) {
    (void)in_sizes; (void)n_in; (void)out_size;
    const float* x    = (const float*)d_in[0];
    const float* gw   = (const float*)d_in[1];
    const float* gb   = (const float*)d_in[2];
    const float* wgu  = (const float*)d_in[3];
    const float* wd   = (const float*)d_in[4];
    const float* wsgu = (const float*)d_in[5];
    const float* wsd  = (const float*)d_in[6];
    float* out = (float*)d_out;

    float* h_shared = sym_f(g_h_shared);
    float* h_moe    = sym_f(g_h_moe);
    float* y_moe    = sym_f(g_y_moe);
    float* x_t      = sym_f(g_x_t);
    float* wgu_t    = sym_f(g_wgu_t);
    float* wd_t     = sym_f(g_wd_t);
    float* wsgu_t   = sym_f(g_wsgu_t);
    float* wsd_t    = sym_f(g_wsd_t);

    cudaFuncSetAttribute(tgemm<false, true,  false, 0, true >, cudaFuncAttributeMaxDynamicSharedMemorySize, SM_BYTES);
    cudaFuncSetAttribute(tgemm<false, false, false, 0, false>, cudaFuncAttributeMaxDynamicSharedMemorySize, SM_BYTES);
    cudaFuncSetAttribute(tgemm<true,  true,  false, 2, true >, cudaFuncAttributeMaxDynamicSharedMemorySize, SM_BYTES);
    cudaFuncSetAttribute(tgemm<true,  false, true,  0, false>, cudaFuncAttributeMaxDynamicSharedMemorySize, SM_BYTES);

    // tf32 pre-conversion passes
    cvt_kernel<<<2048, 256>>>((const float4*)x,    (float4*)x_t,    (int)((size_t)T_TOK * DDIM / 4));
    cvt_kernel<<<4096, 256>>>((const float4*)wgu,  (float4*)wgu_t,  (int)((size_t)NEXP * DDIM * 2 * IDIM / 4));
    cvt_kernel<<<4096, 256>>>((const float4*)wd,   (float4*)wd_t,   (int)((size_t)NEXP * IDIM * DDIM / 4));
    cvt_kernel<<<2048, 256>>>((const float4*)wsgu, (float4*)wsgu_t, (int)((size_t)DDIM * 2 * SIDIM / 4));
    cvt_kernel<<<2048, 256>>>((const float4*)wsd,  (float4*)wsd_t,  (int)((size_t)SIDIM * DDIM / 4));

    init_kernel<<<1, 32>>>();
    router_kernel<<<T_TOK / 8, 256>>>(x, gw, gb);

    // shared gate_up + SwiGLU: x_t[T,D] @ wsgu_t[D,2SI] -> h_shared[T,SI] (tf32-rounded)
    tgemm<false, true, false, 0, true>
        <<<dim3(SIDIM / 64, T_TOK / 128, 1), 256, SM_BYTES>>>(
            x_t, wsgu_t, h_shared, DDIM, DDIM, 2 * SIDIM, SIDIM, 0, SIDIM);

    // shared down: h_shared @ wsd_t -> out (dense write covers poison)
    tgemm<false, false, false, 0, false>
        <<<dim3(DDIM / 128, T_TOK / 128, 1), 256, SM_BYTES>>>(
            h_shared, wsd_t, out, SIDIM, SIDIM, DDIM, DDIM, 0, 0);

    // routed gate_up + SwiGLU (gather tokens): x_t @ wgu_t[e] -> h_moe[slot, I] (tf32-rounded)
    tgemm<true, true, false, 2, true>
        <<<dim3(IDIM / 64, T_TOK / 128, NEXP), 256, SM_BYTES>>>(
            x_t, wgu_t, h_moe, DDIM, DDIM, 2 * IDIM, IDIM,
            (long long)DDIM * 2 * IDIM, IDIM);

    // routed down (gather slots, scale): h_moe @ wd_t[e] -> y_moe[slot, D]
    tgemm<true, false, true, 0, false>
        <<<dim3(DDIM / 128, T_TOK / 128, NEXP), 256, SM_BYTES>>>(
            h_moe, wd_t, y_moe, IDIM, IDIM, DDIM, DDIM,
            (long long)IDIM * DDIM, 0);

    combine_kernel<<<(T_TOK * DDIM / 4 + 255) / 256, 256>>>(out);
}